// round 12
// baseline (speedup 1.0000x reference)
#include <cuda_runtime.h>
#include <cuda_bf16.h>
#include <cstdint>

#define DI __device__ __forceinline__

static constexpr int Bn = 4096;
static constexpr int Dn = 1024;
static constexpr int Cn = 5000;
static constexpr int CP = 5120;
static constexpr int ROWS3 = 3 * Bn;

static constexpr int MT = 128, NT = 128, KC = 64;
static constexpr int NKC = Dn / KC;      // 16
static constexpr int NTN = CP / NT;      // 40
static constexpr int NTM = Bn / MT;      // 32
static constexpr int TILES = NTM * NTN;  // 1280

// 4-stage pipeline: stage = 32KB (A 16KB + B 16KB), e2s after
static constexpr int STAGE_SZ = 32768;
static constexpr int SM_E2 = 4 * STAGE_SZ;          // 131072
static constexpr int SMEM_SZ = SM_E2 + NT * 4;      // 131584

__device__ __nv_bfloat16 g_abf[(size_t)Bn * Dn];
__device__ __nv_bfloat16 g_ebf[(size_t)CP * Dn];
__device__ float g_a2[Bn];
__device__ float g_e2[CP];
__device__ unsigned g_minv[Bn];
__device__ float g_refv[Bn];
__device__ float g_acc[3];

DI uint32_t smem_u32(const void* p) {
    uint32_t a;
    asm("{ .reg .u64 t; cvta.to.shared.u64 t, %1; cvt.u32.u64 %0, t; }" : "=r"(a) : "l"(p));
    return a;
}
DI uint32_t swz(uint32_t o) { return o ^ ((o >> 3) & 0x70); }
DI void cp16(uint32_t dst, const void* src) {
    asm volatile("cp.async.cg.shared.global [%0], [%1], 16;" :: "r"(dst), "l"(src));
}
DI void cp_commit() { asm volatile("cp.async.commit_group;" ::: "memory"); }
template <int N> DI void cp_wait() {
    asm volatile("cp.async.wait_group %0;" :: "n"(N) : "memory");
}
DI void ldsm4(uint32_t* r, uint32_t addr) {
    asm volatile("ldmatrix.sync.aligned.m8n8.x4.shared.b16 {%0,%1,%2,%3}, [%4];"
                 : "=r"(r[0]), "=r"(r[1]), "=r"(r[2]), "=r"(r[3]) : "r"(addr));
}
DI void mma16816(float* c, const uint32_t* a, uint32_t b0, uint32_t b1) {
    asm volatile(
        "mma.sync.aligned.m16n8k16.row.col.f32.bf16.bf16.f32 "
        "{%0,%1,%2,%3}, {%4,%5,%6,%7}, {%8,%9}, {%0,%1,%2,%3};"
        : "+f"(c[0]), "+f"(c[1]), "+f"(c[2]), "+f"(c[3])
        : "r"(a[0]), "r"(a[1]), "r"(a[2]), "r"(a[3]), "r"(b0), "r"(b1));
}
DI unsigned encf(float f) {
    unsigned u = __float_as_uint(f);
    return (u & 0x80000000u) ? ~u : (u | 0x80000000u);
}
DI float decf(unsigned u) {
    return (u & 0x80000000u) ? __uint_as_float(u & 0x7FFFFFFFu) : __uint_as_float(~u);
}
DI unsigned packbf2(float a, float b) {
    __nv_bfloat162 h = __floats2bfloat162_rn(a, b);
    return *reinterpret_cast<unsigned*>(&h);
}

__global__ void init_kernel() {
    int i = blockIdx.x * 256 + threadIdx.x;
    if (i < Bn) g_minv[i] = 0xFFFFFFFFu;
    if (i < 3) g_acc[i] = 0.f;
}

__global__ void __launch_bounds__(128) prep_anchor_kernel(const float* __restrict__ a) {
    int r = blockIdx.x, tid = threadIdx.x, wid = tid >> 5, lane = tid & 31;
    const float4* src = (const float4*)(a + (size_t)r * Dn);
    uint2* dst = (uint2*)(g_abf + (size_t)r * Dn);
    float s = 0.f;
#pragma unroll
    for (int i = 0; i < 2; i++) {
        int idx = tid + i * 128;
        float4 v = src[idx];
        s += v.x * v.x + v.y * v.y + v.z * v.z + v.w * v.w;
        dst[idx] = make_uint2(packbf2(v.x, v.y), packbf2(v.z, v.w));
    }
#pragma unroll
    for (int o = 16; o; o >>= 1) s += __shfl_xor_sync(0xffffffffu, s, o);
    __shared__ float red[4];
    if (lane == 0) red[wid] = s;
    __syncthreads();
    if (tid == 0) g_a2[r] = red[0] + red[1] + red[2] + red[3];
}

__global__ void __launch_bounds__(128) prep_ex_kernel(const float* __restrict__ e) {
    int r = blockIdx.x, tid = threadIdx.x, wid = tid >> 5, lane = tid & 31;
    uint2* dst = (uint2*)(g_ebf + (size_t)r * Dn);
    if (r >= Cn) {
#pragma unroll
        for (int i = 0; i < 2; i++) dst[tid + i * 128] = make_uint2(0u, 0u);
        if (tid == 0) g_e2[r] = __int_as_float(0x7f800000);
        return;
    }
    const float4* src = (const float4*)(e + (size_t)r * Dn);
    float s = 0.f;
#pragma unroll
    for (int i = 0; i < 2; i++) {
        int idx = tid + i * 128;
        float4 v = src[idx];
        s += v.x * v.x + v.y * v.y + v.z * v.z + v.w * v.w;
        dst[idx] = make_uint2(packbf2(v.x, v.y), packbf2(v.z, v.w));
    }
#pragma unroll
    for (int o = 16; o; o >>= 1) s += __shfl_xor_sync(0xffffffffu, s, o);
    __shared__ float red[4];
    if (lane == 0) red[wid] = s;
    __syncthreads();
    if (tid == 0) g_e2[r] = red[0] + red[1] + red[2] + red[3];
}

__global__ void __launch_bounds__(256) softmax_kernel(const float* __restrict__ outs,
                                                      const int* __restrict__ la,
                                                      const int* __restrict__ ln) {
    __shared__ __align__(16) float rowbuf[Cn];
    __shared__ float red[8];
    __shared__ float Msh;
    int r = blockIdx.x, tid = threadIdx.x, wid = tid >> 5, lane = tid & 31;
    const float4* src = (const float4*)(outs + (size_t)r * Cn);
    float m = -3.4e38f;
#pragma unroll
    for (int i = 0; i < 5; i++) {
        int idx = tid + i * 256;
        if (idx < Cn / 4) {
            float4 v = src[idx];
            ((float4*)rowbuf)[idx] = v;
            m = fmaxf(fmaxf(m, fmaxf(v.x, v.y)), fmaxf(v.z, v.w));
        }
    }
#pragma unroll
    for (int o = 16; o; o >>= 1) m = fmaxf(m, __shfl_xor_sync(0xffffffffu, m, o));
    if (lane == 0) red[wid] = m;
    __syncthreads();
    if (tid == 0) {
        float M = red[0];
#pragma unroll
        for (int i = 1; i < 8; i++) M = fmaxf(M, red[i]);
        Msh = M;
    }
    __syncthreads();
    float M = Msh, s = 0.f;
#pragma unroll
    for (int i = 0; i < 5; i++) {
        int idx = tid + i * 256;
        if (idx < Cn / 4) {
            float4 v = ((float4*)rowbuf)[idx];
            s += __expf(v.x - M) + __expf(v.y - M) + __expf(v.z - M) + __expf(v.w - M);
        }
    }
#pragma unroll
    for (int o = 16; o; o >>= 1) s += __shfl_xor_sync(0xffffffffu, s, o);
    if (lane == 0) red[wid] = s;
    __syncthreads();
    if (tid == 0) {
        float S = 0.f;
#pragma unroll
        for (int i = 0; i < 8; i++) S += red[i];
        int lab = (r < 2 * Bn) ? la[r & (Bn - 1)] : ln[r - 2 * Bn];
        float xl = rowbuf[lab];
        atomicAdd(&g_acc[0], -(xl - M - logf(S)));
    }
}

__global__ void __launch_bounds__(128) triplet_kernel(const float* __restrict__ a,
                                                      const float* __restrict__ p,
                                                      const float* __restrict__ n) {
    int r = blockIdx.x, tid = threadIdx.x, wid = tid >> 5, lane = tid & 31;
    const float4* A = (const float4*)(a + (size_t)r * Dn);
    const float4* P = (const float4*)(p + (size_t)r * Dn);
    const float4* N = (const float4*)(n + (size_t)r * Dn);
    float sp = 0.f, sn = 0.f;
#pragma unroll
    for (int i = 0; i < 2; i++) {
        int idx = tid + i * 128;
        float4 va = A[idx], vp = P[idx], vn = N[idx];
        float d0 = va.x - vp.x, d1 = va.y - vp.y, d2 = va.z - vp.z, d3 = va.w - vp.w;
        sp += d0 * d0 + d1 * d1 + d2 * d2 + d3 * d3;
        d0 = va.x - vn.x; d1 = va.y - vn.y; d2 = va.z - vn.z; d3 = va.w - vn.w;
        sn += d0 * d0 + d1 * d1 + d2 * d2 + d3 * d3;
    }
#pragma unroll
    for (int o = 16; o; o >>= 1) {
        sp += __shfl_xor_sync(0xffffffffu, sp, o);
        sn += __shfl_xor_sync(0xffffffffu, sn, o);
    }
    __shared__ float rp[4], rn[4];
    if (lane == 0) { rp[wid] = sp; rn[wid] = sn; }
    __syncthreads();
    if (tid == 0) {
        float tp = rp[0] + rp[1] + rp[2] + rp[3];
        float tn = rn[0] + rn[1] + rn[2] + rn[3];
        atomicAdd(&g_acc[1], fmaxf(sqrtf(tp) - sqrtf(tn), 0.f));
    }
}

// mma.sync bf16 GEMM: per-CTA 128x128 tile of (anchor . exemplar^T), fused
// min / label-gather epilogue on e2 - 2*dot.
__global__ void __launch_bounds__(256, 1) center_gemm_kernel(const int* __restrict__ labels) {
    extern __shared__ __align__(1024) char smem[];
    const uint32_t sb = smem_u32(smem);
    const int tid = threadIdx.x;
    const int warp = tid >> 5, lane = tid & 31;
    const int mw = (warp >> 2) * 64;   // warp M offset (0/64)
    const int nw = (warp & 3) * 32;    // warp N offset (0/32/64/96)

    const int tile = blockIdx.x;
    const int mt = tile / NTN, nt = tile % NTN;
    const int m0 = mt * MT, n0 = nt * NT;

    float* e2s = (float*)(smem + SM_E2);
    if (tid < NT) e2s[tid] = g_e2[n0 + tid];

    float c[4][4][4];
#pragma unroll
    for (int mi = 0; mi < 4; mi++)
#pragma unroll
        for (int ni = 0; ni < 4; ni++)
#pragma unroll
            for (int j = 0; j < 4; j++) c[mi][ni][j] = 0.f;

    auto issue = [&](int k) {
        uint32_t ab = sb + (k & 3) * STAGE_SZ;
        uint32_t bb = ab + 16384;
        int kc = k * KC;
#pragma unroll
        for (int i = 0; i < 8; i++) {
            int idx = tid + i * 256;
            if (idx < 1024) {
                int row = idx >> 3, seg = idx & 7;
                cp16(ab + swz(row * 128 + seg * 16),
                     g_abf + (size_t)(m0 + row) * Dn + kc + seg * 8);
            } else {
                int j = idx - 1024, row = j >> 3, seg = j & 7;
                cp16(bb + swz(row * 128 + seg * 16),
                     g_ebf + (size_t)(n0 + row) * Dn + kc + seg * 8);
            }
        }
        cp_commit();
    };

    issue(0); issue(1); issue(2);

    for (int k = 0; k < NKC; k++) {
        if (k + 3 < NKC) issue(k + 3);
        if (k < NKC - 3)       cp_wait<3>();
        else if (k == NKC - 3) cp_wait<2>();
        else if (k == NKC - 2) cp_wait<1>();
        else                   cp_wait<0>();
        __syncthreads();

        uint32_t ab = sb + (k & 3) * STAGE_SZ;
        uint32_t bb = ab + 16384;
        const uint32_t lrow = lane & 15;
        const uint32_t lhalf = (lane >> 4) * 16;
#pragma unroll
        for (int ks = 0; ks < 4; ks++) {
            uint32_t a[4][4], b[2][4];
            uint32_t kbyte = ks * 32 + lhalf;
#pragma unroll
            for (int mi = 0; mi < 4; mi++)
                ldsm4(a[mi], ab + swz((mw + mi * 16 + lrow) * 128 + kbyte));
#pragma unroll
            for (int g = 0; g < 2; g++)
                ldsm4(b[g], bb + swz((nw + g * 16 + lrow) * 128 + kbyte));
#pragma unroll
            for (int mi = 0; mi < 4; mi++)
#pragma unroll
                for (int ni = 0; ni < 4; ni++)
                    mma16816(c[mi][ni], a[mi], b[ni >> 1][ni & 1], b[ni >> 1][2 + (ni & 1)]);
        }
        __syncthreads();
    }

    // Epilogue: v = e2 - 2*dot ; per-row min + label gather
#pragma unroll
    for (int mi = 0; mi < 4; mi++) {
        int rg0 = m0 + mw + mi * 16 + (lane >> 2);
        int rg1 = rg0 + 8;
        int lab0 = labels[rg0] - n0;
        int lab1 = labels[rg1] - n0;
        float mn0 = __int_as_float(0x7f800000);
        float mn1 = mn0;
#pragma unroll
        for (int ni = 0; ni < 4; ni++) {
            int lc = nw + ni * 8 + 2 * (lane & 3);
            float e0 = e2s[lc], e1 = e2s[lc + 1];
            float v00 = fmaf(-2.f, c[mi][ni][0], e0);
            float v01 = fmaf(-2.f, c[mi][ni][1], e1);
            float v10 = fmaf(-2.f, c[mi][ni][2], e0);
            float v11 = fmaf(-2.f, c[mi][ni][3], e1);
            mn0 = fminf(mn0, fminf(v00, v01));
            mn1 = fminf(mn1, fminf(v10, v11));
            if (lc == lab0) g_refv[rg0] = v00;
            if (lc + 1 == lab0) g_refv[rg0] = v01;
            if (lc == lab1) g_refv[rg1] = v10;
            if (lc + 1 == lab1) g_refv[rg1] = v11;
        }
        mn0 = fminf(mn0, __shfl_xor_sync(0xffffffffu, mn0, 1));
        mn0 = fminf(mn0, __shfl_xor_sync(0xffffffffu, mn0, 2));
        mn1 = fminf(mn1, __shfl_xor_sync(0xffffffffu, mn1, 1));
        mn1 = fminf(mn1, __shfl_xor_sync(0xffffffffu, mn1, 2));
        if ((lane & 3) == 0) {
            atomicMin(&g_minv[rg0], encf(mn0));
            atomicMin(&g_minv[rg1], encf(mn1));
        }
    }
}

__global__ void __launch_bounds__(256) center_reduce_kernel() {
    int i = blockIdx.x * 256 + threadIdx.x;
    int wid = threadIdx.x >> 5, lane = threadIdx.x & 31;
    float a2 = g_a2[i];
    float dc = sqrtf(fmaxf(a2 + decf(g_minv[i]), 0.f));
    float dr = sqrtf(fmaxf(a2 + g_refv[i], 0.f));
    float c = fmaxf(dr - dc, 0.f);
#pragma unroll
    for (int o = 16; o; o >>= 1) c += __shfl_xor_sync(0xffffffffu, c, o);
    __shared__ float red[8];
    if (lane == 0) red[wid] = c;
    __syncthreads();
    if (threadIdx.x == 0) {
        float S = 0.f;
#pragma unroll
        for (int j = 0; j < 8; j++) S += red[j];
        atomicAdd(&g_acc[2], S);
    }
}

__global__ void finalize_kernel(float* out) {
    float sm = g_acc[0] / (float)ROWS3;
    float tr = g_acc[1];
    float ct = g_acc[2];
    out[0] = sm + tr + 0.5f * ct;
    out[1] = tr;
    out[2] = sm;
    out[3] = ct;
}

extern "C" void kernel_launch(void* const* d_in, const int* in_sizes, int n_in,
                              void* d_out, int out_size) {
    const float* anchor   = (const float*)d_in[0];
    const float* positive = (const float*)d_in[1];
    const float* negative = (const float*)d_in[2];
    const float* outputs  = (const float*)d_in[3];
    const int* la         = (const int*)d_in[4];
    const int* ln         = (const int*)d_in[5];
    const float* exem     = (const float*)d_in[6];
    float* out = (float*)d_out;

    cudaFuncSetAttribute(center_gemm_kernel,
                         cudaFuncAttributeMaxDynamicSharedMemorySize, SMEM_SZ);

    init_kernel<<<16, 256>>>();
    prep_anchor_kernel<<<Bn, 128>>>(anchor);
    prep_ex_kernel<<<CP, 128>>>(exem);
    center_gemm_kernel<<<TILES, 256, SMEM_SZ>>>(la);
    softmax_kernel<<<ROWS3, 256>>>(outputs, la, ln);
    triplet_kernel<<<Bn, 128>>>(anchor, positive, negative);
    center_reduce_kernel<<<Bn / 256, 256>>>();
    finalize_kernel<<<1, 1>>>(out);
}

// round 14
// speedup vs baseline: 1.1495x; 1.1495x over previous
#include <cuda_runtime.h>
#include <cuda_bf16.h>
#include <cstdint>

#define DI __device__ __forceinline__

static constexpr int Bn = 4096;
static constexpr int Dn = 1024;
static constexpr int Cn = 5000;
static constexpr int CP = 5120;
static constexpr int ROWS3 = 3 * Bn;

static constexpr int MT = 128, NT = 128, KC = 64;
static constexpr int NKC = Dn / KC;      // 16
static constexpr int NTN = CP / NT;      // 40
static constexpr int NTM = Bn / MT;      // 32
static constexpr int TILES = NTM * NTN;  // 1280

// 3-stage pipeline: stage = 32KB (A 16KB + B 16KB); 2 CTAs/SM
static constexpr int STAGE_SZ = 32768;
static constexpr int SM_E2 = 3 * STAGE_SZ;          // 98304
static constexpr int SMEM_SZ = SM_E2 + NT * 4;      // 98816

__device__ __nv_bfloat16 g_abf[(size_t)Bn * Dn];
__device__ __nv_bfloat16 g_ebf[(size_t)CP * Dn];
__device__ float g_a2[Bn];
__device__ float g_e2[CP];
__device__ unsigned g_minv[Bn];
__device__ float g_refv[Bn];
__device__ float g_acc[3];

DI uint32_t smem_u32(const void* p) {
    uint32_t a;
    asm("{ .reg .u64 t; cvta.to.shared.u64 t, %1; cvt.u32.u64 %0, t; }" : "=r"(a) : "l"(p));
    return a;
}
DI uint32_t swz(uint32_t o) { return o ^ ((o >> 3) & 0x70); }
DI void cp16(uint32_t dst, const void* src) {
    asm volatile("cp.async.cg.shared.global [%0], [%1], 16;" :: "r"(dst), "l"(src));
}
DI void cp_commit() { asm volatile("cp.async.commit_group;" ::: "memory"); }
template <int N> DI void cp_wait() {
    asm volatile("cp.async.wait_group %0;" :: "n"(N) : "memory");
}
DI void ldsm4(uint32_t* r, uint32_t addr) {
    asm volatile("ldmatrix.sync.aligned.m8n8.x4.shared.b16 {%0,%1,%2,%3}, [%4];"
                 : "=r"(r[0]), "=r"(r[1]), "=r"(r[2]), "=r"(r[3]) : "r"(addr));
}
DI void mma16816(float* c, const uint32_t* a, uint32_t b0, uint32_t b1) {
    asm volatile(
        "mma.sync.aligned.m16n8k16.row.col.f32.bf16.bf16.f32 "
        "{%0,%1,%2,%3}, {%4,%5,%6,%7}, {%8,%9}, {%0,%1,%2,%3};"
        : "+f"(c[0]), "+f"(c[1]), "+f"(c[2]), "+f"(c[3])
        : "r"(a[0]), "r"(a[1]), "r"(a[2]), "r"(a[3]), "r"(b0), "r"(b1));
}
DI unsigned encf(float f) {
    unsigned u = __float_as_uint(f);
    return (u & 0x80000000u) ? ~u : (u | 0x80000000u);
}
DI float decf(unsigned u) {
    return (u & 0x80000000u) ? __uint_as_float(u & 0x7FFFFFFFu) : __uint_as_float(~u);
}
DI unsigned packbf2(float a, float b) {
    __nv_bfloat162 h = __floats2bfloat162_rn(a, b);
    return *reinterpret_cast<unsigned*>(&h);
}

__global__ void init_kernel() {
    int i = blockIdx.x * 256 + threadIdx.x;
    if (i < Bn) g_minv[i] = 0xFFFFFFFFu;
    if (i < 3) g_acc[i] = 0.f;
}

// anchor: bf16 convert + |a|^2 + triplet hinge (reads a,p,n once)
__global__ void __launch_bounds__(128) prep_anchor_triplet_kernel(const float* __restrict__ a,
                                                                  const float* __restrict__ p,
                                                                  const float* __restrict__ n) {
    int r = blockIdx.x, tid = threadIdx.x, wid = tid >> 5, lane = tid & 31;
    const float4* A = (const float4*)(a + (size_t)r * Dn);
    const float4* P = (const float4*)(p + (size_t)r * Dn);
    const float4* N = (const float4*)(n + (size_t)r * Dn);
    uint2* dst = (uint2*)(g_abf + (size_t)r * Dn);
    float s = 0.f, sp = 0.f, sn = 0.f;
#pragma unroll
    for (int i = 0; i < 2; i++) {
        int idx = tid + i * 128;
        float4 va = A[idx], vp = P[idx], vn = N[idx];
        s += va.x * va.x + va.y * va.y + va.z * va.z + va.w * va.w;
        dst[idx] = make_uint2(packbf2(va.x, va.y), packbf2(va.z, va.w));
        float d0 = va.x - vp.x, d1 = va.y - vp.y, d2 = va.z - vp.z, d3 = va.w - vp.w;
        sp += d0 * d0 + d1 * d1 + d2 * d2 + d3 * d3;
        d0 = va.x - vn.x; d1 = va.y - vn.y; d2 = va.z - vn.z; d3 = va.w - vn.w;
        sn += d0 * d0 + d1 * d1 + d2 * d2 + d3 * d3;
    }
#pragma unroll
    for (int o = 16; o; o >>= 1) {
        s  += __shfl_xor_sync(0xffffffffu, s, o);
        sp += __shfl_xor_sync(0xffffffffu, sp, o);
        sn += __shfl_xor_sync(0xffffffffu, sn, o);
    }
    __shared__ float ra[4], rp[4], rn[4];
    if (lane == 0) { ra[wid] = s; rp[wid] = sp; rn[wid] = sn; }
    __syncthreads();
    if (tid == 0) {
        g_a2[r] = ra[0] + ra[1] + ra[2] + ra[3];
        float tp = rp[0] + rp[1] + rp[2] + rp[3];
        float tn = rn[0] + rn[1] + rn[2] + rn[3];
        atomicAdd(&g_acc[1], fmaxf(sqrtf(tp) - sqrtf(tn), 0.f));
    }
}

__global__ void __launch_bounds__(128) prep_ex_kernel(const float* __restrict__ e) {
    int r = blockIdx.x, tid = threadIdx.x, wid = tid >> 5, lane = tid & 31;
    uint2* dst = (uint2*)(g_ebf + (size_t)r * Dn);
    if (r >= Cn) {
#pragma unroll
        for (int i = 0; i < 2; i++) dst[tid + i * 128] = make_uint2(0u, 0u);
        if (tid == 0) g_e2[r] = __int_as_float(0x7f800000);
        return;
    }
    const float4* src = (const float4*)(e + (size_t)r * Dn);
    float s = 0.f;
#pragma unroll
    for (int i = 0; i < 2; i++) {
        int idx = tid + i * 128;
        float4 v = src[idx];
        s += v.x * v.x + v.y * v.y + v.z * v.z + v.w * v.w;
        dst[idx] = make_uint2(packbf2(v.x, v.y), packbf2(v.z, v.w));
    }
#pragma unroll
    for (int o = 16; o; o >>= 1) s += __shfl_xor_sync(0xffffffffu, s, o);
    __shared__ float red[4];
    if (lane == 0) red[wid] = s;
    __syncthreads();
    if (tid == 0) g_e2[r] = red[0] + red[1] + red[2] + red[3];
}

__global__ void __launch_bounds__(256) softmax_kernel(const float* __restrict__ outs,
                                                      const int* __restrict__ la,
                                                      const int* __restrict__ ln) {
    __shared__ __align__(16) float rowbuf[Cn];
    __shared__ float red[8];
    __shared__ float Msh;
    int r = blockIdx.x, tid = threadIdx.x, wid = tid >> 5, lane = tid & 31;
    const float4* src = (const float4*)(outs + (size_t)r * Cn);
    float m = -3.4e38f;
#pragma unroll
    for (int i = 0; i < 5; i++) {
        int idx = tid + i * 256;
        if (idx < Cn / 4) {
            float4 v = src[idx];
            ((float4*)rowbuf)[idx] = v;
            m = fmaxf(fmaxf(m, fmaxf(v.x, v.y)), fmaxf(v.z, v.w));
        }
    }
#pragma unroll
    for (int o = 16; o; o >>= 1) m = fmaxf(m, __shfl_xor_sync(0xffffffffu, m, o));
    if (lane == 0) red[wid] = m;
    __syncthreads();
    if (tid == 0) {
        float M = red[0];
#pragma unroll
        for (int i = 1; i < 8; i++) M = fmaxf(M, red[i]);
        Msh = M;
    }
    __syncthreads();
    float M = Msh, s = 0.f;
#pragma unroll
    for (int i = 0; i < 5; i++) {
        int idx = tid + i * 256;
        if (idx < Cn / 4) {
            float4 v = ((float4*)rowbuf)[idx];
            s += __expf(v.x - M) + __expf(v.y - M) + __expf(v.z - M) + __expf(v.w - M);
        }
    }
#pragma unroll
    for (int o = 16; o; o >>= 1) s += __shfl_xor_sync(0xffffffffu, s, o);
    if (lane == 0) red[wid] = s;
    __syncthreads();
    if (tid == 0) {
        float S = 0.f;
#pragma unroll
        for (int i = 0; i < 8; i++) S += red[i];
        int lab = (r < 2 * Bn) ? la[r & (Bn - 1)] : ln[r - 2 * Bn];
        float xl = rowbuf[lab];
        atomicAdd(&g_acc[0], -(xl - M - logf(S)));
    }
}

// mma.sync bf16 GEMM, 3-stage cp.async pipeline, 2 CTAs/SM.
__global__ void __launch_bounds__(256, 2) center_gemm_kernel(const int* __restrict__ labels) {
    extern __shared__ __align__(1024) char smem[];
    const uint32_t sb = smem_u32(smem);
    const int tid = threadIdx.x;
    const int warp = tid >> 5, lane = tid & 31;
    const int mw = (warp >> 2) * 64;
    const int nw = (warp & 3) * 32;

    const int tile = blockIdx.x;
    const int mt = tile / NTN, nt = tile % NTN;
    const int m0 = mt * MT, n0 = nt * NT;

    float* e2s = (float*)(smem + SM_E2);
    if (tid < NT) e2s[tid] = g_e2[n0 + tid];

    float c[4][4][4];
#pragma unroll
    for (int mi = 0; mi < 4; mi++)
#pragma unroll
        for (int ni = 0; ni < 4; ni++)
#pragma unroll
            for (int j = 0; j < 4; j++) c[mi][ni][j] = 0.f;

    auto issue = [&](int k) {
        uint32_t ab = sb + (k % 3) * STAGE_SZ;
        uint32_t bb = ab + 16384;
        int kc = k * KC;
#pragma unroll
        for (int i = 0; i < 8; i++) {
            int idx = tid + i * 256;
            if (idx < 1024) {
                int row = idx >> 3, seg = idx & 7;
                cp16(ab + swz(row * 128 + seg * 16),
                     g_abf + (size_t)(m0 + row) * Dn + kc + seg * 8);
            } else {
                int j = idx - 1024, row = j >> 3, seg = j & 7;
                cp16(bb + swz(row * 128 + seg * 16),
                     g_ebf + (size_t)(n0 + row) * Dn + kc + seg * 8);
            }
        }
        cp_commit();
    };

    issue(0); issue(1);

    for (int k = 0; k < NKC; k++) {
        if (k + 2 < NKC) issue(k + 2);
        if (k < NKC - 2)       cp_wait<2>();
        else if (k == NKC - 2) cp_wait<1>();
        else                   cp_wait<0>();
        __syncthreads();

        uint32_t ab = sb + (k % 3) * STAGE_SZ;
        uint32_t bb = ab + 16384;
        const uint32_t lrow = lane & 15;
        const uint32_t lhalf = (lane >> 4) * 16;
#pragma unroll
        for (int ks = 0; ks < 4; ks++) {
            uint32_t a[4][4], b[2][4];
            uint32_t kbyte = ks * 32 + lhalf;
#pragma unroll
            for (int mi = 0; mi < 4; mi++)
                ldsm4(a[mi], ab + swz((mw + mi * 16 + lrow) * 128 + kbyte));
#pragma unroll
            for (int g = 0; g < 2; g++)
                ldsm4(b[g], bb + swz((nw + g * 16 + lrow) * 128 + kbyte));
#pragma unroll
            for (int mi = 0; mi < 4; mi++)
#pragma unroll
                for (int ni = 0; ni < 4; ni++)
                    mma16816(c[mi][ni], a[mi], b[ni >> 1][ni & 1], b[ni >> 1][2 + (ni & 1)]);
        }
        __syncthreads();
    }

    // Epilogue: v = e2 - 2*dot ; per-row min + label gather
#pragma unroll
    for (int mi = 0; mi < 4; mi++) {
        int rg0 = m0 + mw + mi * 16 + (lane >> 2);
        int rg1 = rg0 + 8;
        int lab0 = labels[rg0] - n0;
        int lab1 = labels[rg1] - n0;
        float mn0 = __int_as_float(0x7f800000);
        float mn1 = mn0;
#pragma unroll
        for (int ni = 0; ni < 4; ni++) {
            int lc = nw + ni * 8 + 2 * (lane & 3);
            float e0 = e2s[lc], e1 = e2s[lc + 1];
            float v00 = fmaf(-2.f, c[mi][ni][0], e0);
            float v01 = fmaf(-2.f, c[mi][ni][1], e1);
            float v10 = fmaf(-2.f, c[mi][ni][2], e0);
            float v11 = fmaf(-2.f, c[mi][ni][3], e1);
            mn0 = fminf(mn0, fminf(v00, v01));
            mn1 = fminf(mn1, fminf(v10, v11));
            if (lc == lab0) g_refv[rg0] = v00;
            if (lc + 1 == lab0) g_refv[rg0] = v01;
            if (lc == lab1) g_refv[rg1] = v10;
            if (lc + 1 == lab1) g_refv[rg1] = v11;
        }
        mn0 = fminf(mn0, __shfl_xor_sync(0xffffffffu, mn0, 1));
        mn0 = fminf(mn0, __shfl_xor_sync(0xffffffffu, mn0, 2));
        mn1 = fminf(mn1, __shfl_xor_sync(0xffffffffu, mn1, 1));
        mn1 = fminf(mn1, __shfl_xor_sync(0xffffffffu, mn1, 2));
        if ((lane & 3) == 0) {
            atomicMin(&g_minv[rg0], encf(mn0));
            atomicMin(&g_minv[rg1], encf(mn1));
        }
    }
}

__global__ void __launch_bounds__(256) center_reduce_kernel() {
    int i = blockIdx.x * 256 + threadIdx.x;
    int wid = threadIdx.x >> 5, lane = threadIdx.x & 31;
    float a2 = g_a2[i];
    float dc = sqrtf(fmaxf(a2 + decf(g_minv[i]), 0.f));
    float dr = sqrtf(fmaxf(a2 + g_refv[i], 0.f));
    float c = fmaxf(dr - dc, 0.f);
#pragma unroll
    for (int o = 16; o; o >>= 1) c += __shfl_xor_sync(0xffffffffu, c, o);
    __shared__ float red[8];
    if (lane == 0) red[wid] = c;
    __syncthreads();
    if (threadIdx.x == 0) {
        float S = 0.f;
#pragma unroll
        for (int j = 0; j < 8; j++) S += red[j];
        atomicAdd(&g_acc[2], S);
    }
}

__global__ void finalize_kernel(float* out) {
    float sm = g_acc[0] / (float)ROWS3;
    float tr = g_acc[1];
    float ct = g_acc[2];
    out[0] = sm + tr + 0.5f * ct;
    out[1] = tr;
    out[2] = sm;
    out[3] = ct;
}

extern "C" void kernel_launch(void* const* d_in, const int* in_sizes, int n_in,
                              void* d_out, int out_size) {
    const float* anchor   = (const float*)d_in[0];
    const float* positive = (const float*)d_in[1];
    const float* negative = (const float*)d_in[2];
    const float* outputs  = (const float*)d_in[3];
    const int* la         = (const int*)d_in[4];
    const int* ln         = (const int*)d_in[5];
    const float* exem     = (const float*)d_in[6];
    float* out = (float*)d_out;

    cudaFuncSetAttribute(center_gemm_kernel,
                         cudaFuncAttributeMaxDynamicSharedMemorySize, SMEM_SZ);

    init_kernel<<<16, 256>>>();
    prep_anchor_triplet_kernel<<<Bn, 128>>>(anchor, positive, negative);
    prep_ex_kernel<<<CP, 128>>>(exem);
    center_gemm_kernel<<<TILES, 256, SMEM_SZ>>>(la);
    softmax_kernel<<<ROWS3, 256>>>(outputs, la, ln);
    center_reduce_kernel<<<Bn / 256, 256>>>();
    finalize_kernel<<<1, 1>>>(out);
}